// round 15
// baseline (speedup 1.0000x reference)
#include <cuda_runtime.h>

// Time-varying FIR, scalar FFMA, dual-accumulator  y = A_L + w*(A_R - A_L).
//   y[t] = sum_{k=0..49} x[t-k]*(bL[n][k] + w*(bR[n][k]-bL[n][k]))
//   n=t/80, w=(t%80)/80, left zero pad, right frame clamped (frame 2999: A_R=A_L).
// Persistent 3-chunk pipeline per block: double-buffered smem; global loads for
// chunk c+1 are issued into registers BEFORE computing chunk c, stored after.
// Coefficients staged as a pure reversed copy rc[f][j] = b[min(f0+f,2999)][49-j]
// for f=0..8; the A_R stream for frame fi is simply row fi+1.

#define BATCH     8
#define N_FRAMES  3000
#define FPERIOD   80
#define T_LEN     (N_FRAMES * FPERIOD)   // 240000
#define TAPS      50
#define ORD       49

#define FPB       8                      // frames per chunk
#define SPB       (FPB * FPERIOD)        // 640 samples per chunk
#define TPF       20                     // threads per frame (R=4)
#define THREADS   160                    // 5 warps
#define CCH       3                      // chunks per block
#define GRIDX     (N_FRAMES / FPB / CCH) // 125

#define SXL       704                    // 52 pad + 640 + 12 spare
#define RCSTRIDE  52                     // frame row stride (float4-aligned)
#define RCL       ((FPB + 1) * RCSTRIDE) // 468
#define NCOEF     ((FPB + 1) * TAPS)     // 450 staged coeffs per chunk

__device__ __forceinline__ float4 ldx4(const float* __restrict__ xb, int g) {
    float4 v;
    if (g >= 0 && g + 3 < T_LEN) {
        v = *(const float4*)(xb + g);
    } else {
        v.x = (g + 0 >= 0 && g + 0 < T_LEN) ? xb[g + 0] : 0.0f;
        v.y = (g + 1 >= 0 && g + 1 < T_LEN) ? xb[g + 1] : 0.0f;
        v.z = (g + 2 >= 0 && g + 2 < T_LEN) ? xb[g + 2] : 0.0f;
        v.w = (g + 3 >= 0 && g + 3 < T_LEN) ? xb[g + 3] : 0.0f;
    }
    return v;
}

__global__ __launch_bounds__(THREADS, 7)
void azdf_kernel(const float* __restrict__ x,
                 const float* __restrict__ b,
                 float* __restrict__ y)
{
    __shared__ __align__(16) float sx[2][SXL];
    __shared__ __align__(16) float rc[2][RCL];

    const int tid = threadIdx.x;
    const int bb  = blockIdx.y;
    const int ch0 = blockIdx.x * CCH;

    const float* xb = x + (size_t)bb * T_LEN;
    const float* bp = b + (size_t)bb * N_FRAMES * TAPS;

    // fixed per-thread staging slots
    const int  xv   = tid * 4;            // x float4 dest (<= 636)
    const int  xs   = 640 + tid;          // x scalar dest (tid < 64)
    const bool hasx = (tid < SXL - 640);
    const int  ia = tid, ib = tid + 160, ic = tid + 320;
    const bool hasc = (ic < NCOEF);       // tid < 130
    const int  fa = ia / TAPS, ka = ia % TAPS, sa = fa * RCSTRIDE + (ORD - ka);
    const int  fb = ib / TAPS, kb = ib % TAPS, sb = fb * RCSTRIDE + (ORD - kb);
    const int  fc = ic / TAPS, kc = ic % TAPS, sdc = fc * RCSTRIDE + (ORD - kc);

    // fixed compute assignment
    const int fi  = tid / TPF;            // frame within chunk
    const int sub = tid - fi * TPF;
    const int p0  = sub * 4;              // phase of first sample in frame
    const int s   = fi * FPERIOD + p0;    // sample offset in chunk (mult of 4)

    // ---- prologue: stage chunk ch0 ----
    int f0 = ch0 * FPB;
    int t0 = f0 * FPERIOD;

    float4 px  = ldx4(xb, t0 - 52 + xv);
    float  pxe = 0.0f;
    if (hasx) { int g = t0 - 52 + xs; pxe = (g >= 0 && g < T_LEN) ? xb[g] : 0.0f; }
    float pa = bp[min(f0 + fa, N_FRAMES - 1) * TAPS + ka];
    float pb = bp[min(f0 + fb, N_FRAMES - 1) * TAPS + kb];
    float pc = hasc ? bp[min(f0 + fc, N_FRAMES - 1) * TAPS + kc] : 0.0f;

    *(float4*)&sx[0][xv] = px;
    if (hasx) sx[0][xs] = pxe;
    rc[0][sa] = pa;
    rc[0][sb] = pb;
    if (hasc) rc[0][sdc] = pc;
    __syncthreads();

    #pragma unroll 1
    for (int c = 0; c < CCH; c++) {
        const int cur = c & 1, nxt = cur ^ 1;

        // ---- issue global loads for chunk c+1 (land during compute) ----
        if (c + 1 < CCH) {
            const int f1 = f0 + FPB, t1 = t0 + SPB;
            px = ldx4(xb, t1 - 52 + xv);
            if (hasx) { int g = t1 - 52 + xs; pxe = (g < T_LEN) ? xb[g] : 0.0f; }
            pa = bp[min(f1 + fa, N_FRAMES - 1) * TAPS + ka];
            pb = bp[min(f1 + fb, N_FRAMES - 1) * TAPS + kb];
            if (hasc) pc = bp[min(f1 + fc, N_FRAMES - 1) * TAPS + kc];
        }

        // ---- compute chunk c ----
        const float* sxp = sx[cur];
        const float* rcp = rc[cur];

        float w0 = sxp[s + 3], w1 = sxp[s + 4], w2 = sxp[s + 5], w3 = sxp[s + 6];
        float xlead = sxp[s + 7];

        float a0 = 0.f, a1 = 0.f, a2 = 0.f, a3 = 0.f;   // A_L = sum x*bL
        float r0 = 0.f, r1 = 0.f, r2 = 0.f, r3 = 0.f;   // A_R = sum x*bR

        const float4* clq = (const float4*)(rcp + fi * RCSTRIDE);
        const float4* crq = (const float4*)(rcp + (fi + 1) * RCSTRIDE);
        const float4* xq  = (const float4*)(sxp + s + 8);

        float4 cl = clq[0], cln = clq[1];
        float4 cr = crq[0], crn = crq[1];
        float4 xp = xq[0],  xpn = xq[1];

        #pragma unroll
        for (int j = 0; j < TAPS; j++) {
            if (j >= 4 && (j & 3) == 0) {
                cl = cln; cr = crn;
                int q = (j >> 2) + 1; q = (q < 13) ? q : 12;
                cln = clq[q]; crn = crq[q];
            }
            const int e = j & 3;          // compile-time after unroll
            const float cb = (e == 0) ? cl.x : (e == 1) ? cl.y : (e == 2) ? cl.z : cl.w;
            const float cd = (e == 0) ? cr.x : (e == 1) ? cr.y : (e == 2) ? cr.z : cr.w;

            if (j >= 5 && ((j - 1) & 3) == 0) {
                xp = xpn;
                int q = ((j - 1) >> 2) + 1; q = (q < 13) ? q : 12;
                xpn = xq[q];
            }

            a0 = fmaf(w0, cb, a0);  r0 = fmaf(w0, cd, r0);
            a1 = fmaf(w1, cb, a1);  r1 = fmaf(w1, cd, r1);
            a2 = fmaf(w2, cb, a2);  r2 = fmaf(w2, cd, r2);
            a3 = fmaf(w3, cb, a3);  r3 = fmaf(w3, cd, r3);

            if (j < TAPS - 1) {
                float nx;
                if (j == 0) nx = xlead;
                else {
                    const int ph = (j - 1) & 3;
                    nx = (ph == 0) ? xp.x : (ph == 1) ? xp.y : (ph == 2) ? xp.z : xp.w;
                }
                w0 = w1; w1 = w2; w2 = w3; w3 = nx;
            }
        }

        // epilogue: y = A_L + w*(A_R - A_L), one STG.128
        {
            const float inv = 1.0f / FPERIOD;
            float4 out;
            out.x = fmaf((float)(p0 + 0) * inv, r0 - a0, a0);
            out.y = fmaf((float)(p0 + 1) * inv, r1 - a1, a1);
            out.z = fmaf((float)(p0 + 2) * inv, r2 - a2, a2);
            out.w = fmaf((float)(p0 + 3) * inv, r3 - a3, a3);
            *(float4*)(y + (size_t)bb * T_LEN + t0 + s) = out;
        }

        // ---- commit prefetched chunk c+1 to the other buffer ----
        if (c + 1 < CCH) {
            *(float4*)&sx[nxt][xv] = px;
            if (hasx) sx[nxt][xs] = pxe;
            rc[nxt][sa] = pa;
            rc[nxt][sb] = pb;
            if (hasc) rc[nxt][sdc] = pc;
            __syncthreads();
            f0 += FPB; t0 += SPB;
        }
    }
}

extern "C" void kernel_launch(void* const* d_in, const int* in_sizes, int n_in,
                              void* d_out, int out_size)
{
    const float* x = (const float*)d_in[0];
    const float* b = (const float*)d_in[1];
    if (in_sizes[0] != BATCH * T_LEN) {   // defensive input-order check
        const float* t = x; x = b; b = t;
    }
    dim3 grid(GRIDX, BATCH);              // 125 x 8 = 1000 blocks
    azdf_kernel<<<grid, THREADS>>>(x, b, (float*)d_out);
}

// round 17
// speedup vs baseline: 1.0194x; 1.0194x over previous
#include <cuda_runtime.h>

// Time-varying FIR, scalar FFMA, dual-accumulator  y = A_L + w*(A_R - A_L).
//   y[t] = sum_{k=0..49} x[t-k]*b~[n..n+1][k],  n=t/80, w=(t%80)/80,
//   left zero pad, right frame clamped (frame 2999 -> A_R = A_L).
// 3-chunk pipeline per block with cp.async double-buffered staging: loads for
// chunk c+1 are in flight while chunk c computes; zero prefetch registers.
// Taps iterate k ASCENDING (window slides down) so coefficient rows stage as
// forward copies (cp.async 8B) and all window loads are aligned LDS.128.

#define BATCH     8
#define N_FRAMES  3000
#define FPERIOD   80
#define T_LEN     (N_FRAMES * FPERIOD)   // 240000
#define TAPS      50
#define ORD       49

#define FPB       8                      // frames per chunk
#define SPB       (FPB * FPERIOD)        // 640
#define TPF       20                     // threads per frame (R=4)
#define THREADS   160                    // 5 warps
#define CCH       3                      // chunks per block
#define GRIDX     (N_FRAMES / FPB / CCH) // 125

#define SXL       704                    // 52 left pad + 640 + 12 spare
#define NXG       (SXL / 4)              // 176 16B groups
#define RSTRIDE   52                     // coeff row stride (13 float4)
#define NROWS     (FPB + 1)              // 9 rows (frames f0..f0+8, clamped)
#define RCL       (NROWS * RSTRIDE)      // 468
#define NC8       (NROWS * 25)           // 225 8-byte copy ops

__device__ __forceinline__ unsigned su32(const void* p) {
    return (unsigned)__cvta_generic_to_shared(p);
}

// stage one chunk (x window + 9 coeff rows) into smem via cp.async
__device__ __forceinline__ void stage_chunk(float* __restrict__ sxd,
                                            float* __restrict__ rcd,
                                            const float* __restrict__ xb,
                                            const float* __restrict__ bp,
                                            int f0, int t0, int tid)
{
    // x: sxd[i] = x[t0-52+i], 16B groups; left pad exactly 13 whole groups
    #pragma unroll
    for (int g = tid; g < NXG; g += THREADS) {
        int gs = t0 - 52 + g * 4;
        if (gs < 0) {                        // whole group below 0 (52 = 13*4)
            *(float4*)(sxd + g * 4) = make_float4(0.f, 0.f, 0.f, 0.f);
        } else {
            int rem = T_LEN - gs;            // may be <=0 at far right edge
            int sb  = (rem >= 4) ? 16 : ((rem > 0) ? rem * 4 : 0);
            const float* src = (rem > 0) ? (xb + gs) : xb;
            unsigned dst = su32(sxd + g * 4);
            asm volatile("cp.async.cg.shared.global [%0], [%1], 16, %2;\n"
                         :: "r"(dst), "l"(src), "r"(sb));
        }
    }
    // coeffs: rcd[row*52 + k] = b[min(f0+row, 2999)][k], forward 8B copies
    #pragma unroll
    for (int i = tid; i < NC8; i += THREADS) {
        int row = i / 25, off = i - row * 25;
        int fr  = f0 + row;
        if (fr > N_FRAMES - 1) fr = N_FRAMES - 1;
        const float* src = bp + fr * TAPS + off * 2;
        unsigned dst = su32(rcd + row * RSTRIDE + off * 2);
        asm volatile("cp.async.ca.shared.global [%0], [%1], 8;\n"
                     :: "r"(dst), "l"(src));
    }
}

__global__ __launch_bounds__(THREADS, 8)
void azdf_kernel(const float* __restrict__ x,
                 const float* __restrict__ b,
                 float* __restrict__ y)
{
    __shared__ __align__(16) float sx[2][SXL];
    __shared__ __align__(16) float rc[2][RCL];

    const int tid = threadIdx.x;
    const int bb  = blockIdx.y;
    const int ch0 = blockIdx.x * CCH;

    const float* xb = x + (size_t)bb * T_LEN;
    const float* bp = b + (size_t)bb * N_FRAMES * TAPS;

    int f0 = ch0 * FPB;
    int t0 = f0 * FPERIOD;

    // ---- prologue: stage chunk 0 ----
    stage_chunk(sx[0], rc[0], xb, bp, f0, t0, tid);
    asm volatile("cp.async.commit_group;\n");
    asm volatile("cp.async.wait_group 0;\n");
    __syncthreads();

    const int fi  = tid / TPF;            // frame within chunk
    const int sub = tid - fi * TPF;
    const int p0  = sub * 4;              // phase of first sample in frame
    const int s   = fi * FPERIOD + p0;    // sample offset in chunk (mult of 4)

    #pragma unroll 1
    for (int c = 0; c < CCH; c++) {
        const int cur = c & 1, nxt = cur ^ 1;

        // ---- issue async staging for chunk c+1 (lands during compute) ----
        if (c + 1 < CCH) {
            stage_chunk(sx[nxt], rc[nxt], xb, bp, f0 + FPB, t0 + SPB, tid);
            asm volatile("cp.async.commit_group;\n");
        }

        // ---- compute chunk c ----
        // y[s+m] = sum_k sx[s+3+m+(49-k)] * c_row[k]  (k ascending, window down)
        const float*  sxp = sx[cur];
        const float4* xg4 = (const float4*)(sxp + s);            // s mult of 4
        const float4* clq = (const float4*)(rc[cur] + fi * RSTRIDE);
        const float4* crq = (const float4*)(rc[cur] + (fi + 1) * RSTRIDE);

        float4 wv = xg4[13];              // sx[s+52 .. s+55]
        float w0 = wv.x, w1 = wv.y, w2 = wv.z, w3 = wv.w;   // w_m, m=0..3

        float4 cl = clq[0], cln = clq[1];
        float4 cr = crq[0], crn = crq[1];
        float4 xp = xg4[12], xpn = xg4[11];                 // shift-in groups

        float a0 = 0.f, a1 = 0.f, a2 = 0.f, a3 = 0.f;       // A_L
        float r0 = 0.f, r1 = 0.f, r2 = 0.f, r3 = 0.f;       // A_R

        #pragma unroll
        for (int k = 0; k < TAPS; k++) {
            if (k >= 4 && (k & 3) == 0) {
                cl = cln;  cr = crn;
                int q = (k >> 2) + 1; if (q > 12) q = 12;
                cln = clq[q];  crn = crq[q];
                xp = xpn;
                int g = 11 - (k >> 2); if (g < 0) g = 0;
                xpn = xg4[g];
            }
            const int e = k & 3;          // compile-time after unroll
            const float cb = (e == 0) ? cl.x : (e == 1) ? cl.y : (e == 2) ? cl.z : cl.w;
            const float cd = (e == 0) ? cr.x : (e == 1) ? cr.y : (e == 2) ? cr.z : cr.w;

            a0 = fmaf(w0, cb, a0);  r0 = fmaf(w0, cd, r0);
            a1 = fmaf(w1, cb, a1);  r1 = fmaf(w1, cd, r1);
            a2 = fmaf(w2, cb, a2);  r2 = fmaf(w2, cd, r2);
            a3 = fmaf(w3, cb, a3);  r3 = fmaf(w3, cd, r3);

            if (k < TAPS - 1) {
                // shift-in sx[s+51-k]: group (51-k)>>2 (= xp), element (51-k)&3
                const int ph = (51 - k) & 3;
                const float nx = (ph == 0) ? xp.x : (ph == 1) ? xp.y
                               : (ph == 2) ? xp.z : xp.w;
                w3 = w2; w2 = w1; w1 = w0; w0 = nx;
            }
        }

        // epilogue: y = A_L + w*(A_R - A_L), one STG.128
        {
            const float inv = 1.0f / FPERIOD;
            float4 out;
            out.x = fmaf((float)(p0 + 0) * inv, r0 - a0, a0);
            out.y = fmaf((float)(p0 + 1) * inv, r1 - a1, a1);
            out.z = fmaf((float)(p0 + 2) * inv, r2 - a2, a2);
            out.w = fmaf((float)(p0 + 3) * inv, r3 - a3, a3);
            *(float4*)(y + (size_t)bb * T_LEN + t0 + s) = out;
        }

        if (c + 1 < CCH) {
            asm volatile("cp.async.wait_group 0;\n");
            __syncthreads();
            f0 += FPB;  t0 += SPB;
        }
    }
}

extern "C" void kernel_launch(void* const* d_in, const int* in_sizes, int n_in,
                              void* d_out, int out_size)
{
    const float* x = (const float*)d_in[0];
    const float* b = (const float*)d_in[1];
    if (in_sizes[0] != BATCH * T_LEN) {   // defensive input-order check
        const float* t = x; x = b; b = t;
    }
    dim3 grid(GRIDX, BATCH);              // 125 x 8 = 1000 blocks
    azdf_kernel<<<grid, THREADS>>>(x, b, (float*)d_out);
}